// round 14
// baseline (speedup 1.0000x reference)
#include <cuda_runtime.h>
#include <cuda_fp16.h>

#define BATCH 8
#define C 256
#define HW 4096
#define PT 64
#define TI 128
#define NTI (HW / TI)                // 32
#define NPAIR (NTI * (NTI + 1) / 2)  // 528

// Global scratch
__device__ __half g_xnT_h[(size_t)BATCH * HW * C];  // normalized, pixel-major (p, c)
__device__ float  g_norm [(size_t)BATCH * HW];      // channel L2 norm per pixel
__device__ __half g_t_h  [(size_t)BATCH * C * HW];  // t = Wx+b, c-major (c, p)
__device__ __half g_W_h  [C * C];                   // W fp16
__device__ __half g_Q    [(size_t)BATCH * HW * HW]; // Q = S^2, lower-block-triangle only

__device__ __forceinline__ unsigned smem_u32(const void* p) {
    unsigned a;
    asm("{ .reg .u64 t; cvta.to.shared.u64 t, %1; cvt.u32.u64 %0, t; }" : "=r"(a) : "l"(p));
    return a;
}
__device__ __forceinline__ void cpa16(unsigned dst, const void* src) {
    asm volatile("cp.async.cg.shared.global [%0], [%1], 16;" :: "r"(dst), "l"(src) : "memory");
}
__device__ __forceinline__ void cpa_commit() {
    asm volatile("cp.async.commit_group;" ::: "memory");
}
__device__ __forceinline__ void ldsm_x4(unsigned* r, unsigned addr) {
    asm volatile("ldmatrix.sync.aligned.m8n8.x4.shared.b16 {%0,%1,%2,%3}, [%4];"
                 : "=r"(r[0]), "=r"(r[1]), "=r"(r[2]), "=r"(r[3]) : "r"(addr));
}
__device__ __forceinline__ void ldsm_x4t(unsigned* r, unsigned addr) {
    asm volatile("ldmatrix.sync.aligned.m8n8.x4.trans.shared.b16 {%0,%1,%2,%3}, [%4];"
                 : "=r"(r[0]), "=r"(r[1]), "=r"(r[2]), "=r"(r[3]) : "r"(addr));
}
__device__ __forceinline__ void mma_f16(float d[4], const unsigned a[4], unsigned b0, unsigned b1) {
    asm volatile(
        "mma.sync.aligned.m16n8k16.row.col.f32.f16.f16.f32 "
        "{%0,%1,%2,%3}, {%4,%5,%6,%7}, {%8,%9}, {%0,%1,%2,%3};"
        : "+f"(d[0]), "+f"(d[1]), "+f"(d[2]), "+f"(d[3])
        : "r"(a[0]), "r"(a[1]), "r"(a[2]), "r"(a[3]), "r"(b0), "r"(b1));
}
// fp16-accumulator variant: D/C are 2 regs (f16x2) -> fewer RF ports per HMMA
__device__ __forceinline__ void mma_h16(unsigned d[2], const unsigned a[4], unsigned b0, unsigned b1) {
    asm volatile(
        "mma.sync.aligned.m16n8k16.row.col.f16.f16.f16.f16 "
        "{%0,%1}, {%2,%3,%4,%5}, {%6,%7}, {%0,%1};"
        : "+r"(d[0]), "+r"(d[1])
        : "r"(a[0]), "r"(a[1]), "r"(a[2]), "r"(a[3]), "r"(b0), "r"(b1));
}
__device__ __forceinline__ unsigned pack_h2(float a, float b) {
    __half2 h = __floats2half2_rn(a, b);
    return *reinterpret_cast<unsigned*>(&h);
}

// ---------------------------------------------------------------------------
__global__ void conv_w_kernel(const float* __restrict__ W) {
    int i = (blockIdx.x * 256 + threadIdx.x) * 4;
    float4 v = *reinterpret_cast<const float4*>(W + i);
    uint2 u;
    u.x = pack_h2(v.x, v.y);
    u.y = pack_h2(v.z, v.w);
    *reinterpret_cast<uint2*>(g_W_h + i) = u;
}

// ---------------------------------------------------------------------------
// Prep: invn + write xnT_h (normalized, fp16) + g_norm (fp32)
// ---------------------------------------------------------------------------
__global__ void __launch_bounds__(256, 1)
prep_kernel(const float* __restrict__ x)
{
    extern __shared__ float sm[];
    float* xs   = sm;                  // C * 68
    float* invn = xs + C * 68;         // 64

    const int p0  = blockIdx.x * PT;
    const int b   = blockIdx.y;
    const int tid = threadIdx.x;
    const float* xb = x + (size_t)b * C * HW;

    #pragma unroll
    for (int r = 0; r < 16; ++r) {
        int f4 = r * 256 + tid;
        int c  = f4 >> 4;
        int kq = f4 & 15;
        float4 v = *reinterpret_cast<const float4*>(xb + (size_t)c * HW + p0 + kq * 4);
        *reinterpret_cast<float4*>(xs + c * 68 + kq * 4) = v;
    }
    __syncthreads();

    if (tid < 64) {
        float s = 0.f;
        #pragma unroll 8
        for (int c = 0; c < C; ++c) { float v = xs[c * 68 + tid]; s += v * v; }
        float nrm = fmaxf(sqrtf(s), 1e-12f);
        g_norm[(size_t)b * HW + p0 + tid] = nrm;
        invn[tid] = 1.0f / nrm;
    }
    __syncthreads();

    {
        int p   = tid & 63;
        int grp = tid >> 6;
        float inv = invn[p];
        __half* dn = g_xnT_h + ((size_t)b * HW + p0 + p) * C;
        #pragma unroll
        for (int cc = 0; cc < 16; ++cc) {
            int c = grp * 64 + cc * 4;
            uint2 un;
            un.x = pack_h2(xs[(c + 0) * 68 + p] * inv, xs[(c + 1) * 68 + p] * inv);
            un.y = pack_h2(xs[(c + 2) * 68 + p] * inv, xs[(c + 3) * 68 + p] * inv);
            *reinterpret_cast<uint2*>(dn + c) = un;
        }
    }
}

// ---------------------------------------------------------------------------
// tgemm: t[c][p] = norm[p] * (W @ xn)[c][p] + bias[c]
// ---------------------------------------------------------------------------
#define TG_WS 18432
#define TG_XS 9216
#define TG_SMEM_H (2 * TG_WS + 2 * TG_XS)

__global__ void __launch_bounds__(256, 1)
tgemm_kernel(const float* __restrict__ bias)
{
    extern __shared__ __half smh[];
    const unsigned sbase = smem_u32(smh);

    const int p0  = blockIdx.x * 128;
    const int b   = blockIdx.y;
    const int tid = threadIdx.x;
    const int wid = tid >> 5;
    const int lane = tid & 31;
    const int wm = wid & 3;
    const int wn = wid >> 2;
    const unsigned lrow = (unsigned)(lane & 15);
    const unsigned lk8  = (unsigned)((lane >> 4) * 8);

    const __half* xn_b = g_xnT_h + (size_t)b * HW * C;

    auto issue = [&](int ck) {
        const int k0 = ck * 64;
        const unsigned ws_o = (unsigned)((ck & 1) * TG_WS);
        const unsigned xs_o = (unsigned)(2 * TG_WS + (ck & 1) * TG_XS);
        #pragma unroll
        for (int r = 0; r < 8; ++r) {
            int f = r * 256 + tid;
            int c = f >> 3, ch = f & 7;
            cpa16(sbase + (ws_o + (unsigned)(c * 72 + ch * 8)) * 2,
                  g_W_h + (size_t)c * C + k0 + ch * 8);
        }
        #pragma unroll
        for (int r = 0; r < 4; ++r) {
            int f = r * 256 + tid;
            int p = f >> 3, ch = f & 7;
            cpa16(sbase + (xs_o + (unsigned)(p * 72 + ch * 8)) * 2,
                  xn_b + (size_t)(p0 + p) * C + k0 + ch * 8);
        }
        cpa_commit();
    };

    issue(0);

    float acc[4][8][4];
    #pragma unroll
    for (int m = 0; m < 4; ++m)
        #pragma unroll
        for (int t = 0; t < 8; ++t)
            #pragma unroll
            for (int r = 0; r < 4; ++r) acc[m][t][r] = 0.f;

    for (int ck = 0; ck < 4; ++ck) {
        if (ck + 1 < 4) {
            issue(ck + 1);
            asm volatile("cp.async.wait_group 1;" ::: "memory");
        } else {
            asm volatile("cp.async.wait_group 0;" ::: "memory");
        }
        __syncthreads();
        const unsigned ws_o = (unsigned)((ck & 1) * TG_WS);
        const unsigned xs_o = (unsigned)(2 * TG_WS + (ck & 1) * TG_XS);

        const unsigned aA = sbase + (ws_o + (unsigned)((wm * 64 + lrow) * 72) + lk8) * 2;
        const unsigned aB = sbase + (xs_o + (unsigned)((wn * 64 + lrow) * 72) + lk8) * 2;
        #pragma unroll
        for (int kk = 0; kk < 4; ++kk) {
            unsigned a[4][4], bb[4][4];
            #pragma unroll
            for (int m = 0; m < 4; ++m)
                ldsm_x4(a[m], aA + (unsigned)(m * 16 * 72 * 2) + kk * 32);
            #pragma unroll
            for (int n = 0; n < 4; ++n)
                ldsm_x4(bb[n], aB + (unsigned)(n * 16 * 72 * 2) + kk * 32);
            #pragma unroll
            for (int m = 0; m < 4; ++m)
                #pragma unroll
                for (int n = 0; n < 4; ++n) {
                    mma_f16(acc[m][n * 2 + 0], a[m], bb[n][0], bb[n][2]);
                    mma_f16(acc[m][n * 2 + 1], a[m], bb[n][1], bb[n][3]);
                }
        }
        __syncthreads();
    }

    __half* tb = g_t_h + (size_t)b * C * HW;
    const float* nb = g_norm + (size_t)b * HW;
    #pragma unroll
    for (int m = 0; m < 4; ++m) {
        const int c0 = wm * 64 + m * 16 + (lane >> 2);
        const float bo0 = __ldg(bias + c0);
        const float bo1 = __ldg(bias + c0 + 8);
        #pragma unroll
        for (int t = 0; t < 8; ++t) {
            const int p = p0 + wn * 64 + t * 8 + (lane & 3) * 2;
            float2 n2 = *reinterpret_cast<const float2*>(nb + p);
            *reinterpret_cast<unsigned*>(tb + (size_t)c0 * HW + p) =
                pack_h2(acc[m][t][0] * n2.x + bo0, acc[m][t][1] * n2.y + bo0);
            *reinterpret_cast<unsigned*>(tb + (size_t)(c0 + 8) * HW + p) =
                pack_h2(acc[m][t][2] * n2.x + bo1, acc[m][t][3] * n2.y + bo1);
        }
    }
}

// ---------------------------------------------------------------------------
// qbuild: per (pair, b): S = Xn_i Xn_j^T (128x128, K=256 in four 64-chunks,
//         double-buffered), Q = S^2 -> g_Q[i][j].  Pairs with ti >= tj.
// smem halves: xi 2x(128x72), xj 2x(128x72), qs 128x136 = 108,544 B -> 2 CTAs
// ---------------------------------------------------------------------------
#define QB_XI0 0
#define QB_XI1 9216
#define QB_XJ0 18432
#define QB_XJ1 27648
#define QB_QS  36864
#define Q_SMEM_H 54272

__global__ void __launch_bounds__(256, 2)
qbuild_kernel()
{
    extern __shared__ __half smh[];
    const unsigned sbase = smem_u32(smh);

    const int p   = blockIdx.x;
    const int b   = blockIdx.y;
    const int tid = threadIdx.x;
    const int wid = tid >> 5;
    const int lane = tid & 31;

    int ti = (int)((sqrtf(8.f * (float)p + 1.f) - 1.f) * 0.5f);
    while ((ti + 1) * (ti + 2) / 2 <= p) ++ti;
    while (ti * (ti + 1) / 2 > p) --ti;
    const int tj = p - ti * (ti + 1) / 2;
    const int i0 = ti * TI;
    const int j0 = tj * TI;

    const __half* xnT_b = g_xnT_h + (size_t)b * HW * C;

    const int wm = wid & 3;    // i-strip (32 rows)
    const int wn = wid >> 2;   // j-half (64 cols)
    const unsigned lrow = (unsigned)(lane & 15);
    const unsigned lk8  = (unsigned)((lane >> 4) * 8);

    auto issue = [&](int kc) {
        const int kb = kc * 64;
        const unsigned xi_o = (unsigned)((kc & 1) ? QB_XI1 : QB_XI0);
        const unsigned xj_o = (unsigned)((kc & 1) ? QB_XJ1 : QB_XJ0);
        #pragma unroll
        for (int r = 0; r < 4; ++r) {
            int f = r * 256 + tid;
            int row = f >> 3, ch = f & 7;
            cpa16(sbase + (xi_o + (unsigned)(row * 72 + ch * 8)) * 2,
                  xnT_b + (size_t)(i0 + row) * C + kb + ch * 8);
            cpa16(sbase + (xj_o + (unsigned)(row * 72 + ch * 8)) * 2,
                  xnT_b + (size_t)(j0 + row) * C + kb + ch * 8);
        }
        cpa_commit();
    };

    issue(0);

    float d[2][8][4];
    #pragma unroll
    for (int m = 0; m < 2; ++m)
        #pragma unroll
        for (int t = 0; t < 8; ++t)
            #pragma unroll
            for (int r = 0; r < 4; ++r) d[m][t][r] = 0.f;

    for (int kc = 0; kc < 4; ++kc) {
        if (kc + 1 < 4) {
            issue(kc + 1);
            asm volatile("cp.async.wait_group 1;" ::: "memory");
        } else {
            asm volatile("cp.async.wait_group 0;" ::: "memory");
        }
        __syncthreads();

        const unsigned xi_o = (unsigned)((kc & 1) ? QB_XI1 : QB_XI0);
        const unsigned xj_o = (unsigned)((kc & 1) ? QB_XJ1 : QB_XJ0);
        const unsigned aA = sbase + (xi_o + (unsigned)((wm * 32 + lrow) * 72) + lk8) * 2;
        const unsigned aB = sbase + (xj_o + (unsigned)((wn * 64 + lrow) * 72) + lk8) * 2;

        #pragma unroll
        for (int kk = 0; kk < 4; ++kk) {
            unsigned a[2][4];
            ldsm_x4(a[0], aA + kk * 32);
            ldsm_x4(a[1], aA + 16 * 72 * 2 + kk * 32);
            #pragma unroll
            for (int tt = 0; tt < 4; ++tt) {
                unsigned bb[4];
                ldsm_x4(bb, aB + (unsigned)(tt * 16 * 72 * 2) + kk * 32);
                #pragma unroll
                for (int m = 0; m < 2; ++m) {
                    mma_f16(d[m][tt * 2 + 0], a[m], bb[0], bb[2]);
                    mma_f16(d[m][tt * 2 + 1], a[m], bb[1], bb[3]);
                }
            }
        }
        __syncthreads();
    }

    {
        __half* qsm = smh + QB_QS;
        #pragma unroll
        for (int m = 0; m < 2; ++m) {
            const int r0 = wm * 32 + m * 16 + (lane >> 2);
            #pragma unroll
            for (int t = 0; t < 8; ++t) {
                const int col = wn * 64 + t * 8 + (lane & 3) * 2;
                *reinterpret_cast<unsigned*>(qsm + r0 * 136 + col) =
                    pack_h2(d[m][t][0] * d[m][t][0], d[m][t][1] * d[m][t][1]);
                *reinterpret_cast<unsigned*>(qsm + (r0 + 8) * 136 + col) =
                    pack_h2(d[m][t][2] * d[m][t][2], d[m][t][3] * d[m][t][3]);
            }
        }
    }
    __syncthreads();

    __half* Qb = g_Q + ((size_t)b * HW * HW);
    #pragma unroll
    for (int rr = 0; rr < 16; ++rr) {
        const int r = wid * 16 + rr;
        uint2 v = *reinterpret_cast<const uint2*>(smh + QB_QS + r * 136 + lane * 4);
        *reinterpret_cast<uint2*>(Qb + (size_t)(i0 + r) * HW + j0 + lane * 4) = v;
    }
}

// ---------------------------------------------------------------------------
// propagate: out[b][c][j] = sum_k t[c][k] * Q_sym[k][j]
// CTA: 128 c x 128 j, 128 threads (2x2 grid of 64x64 warp tiles), 2 CTAs/SM,
// K=4096 in 64-chunks, 3-stage cp.async pipeline.
// Chunk accumulation in FP16 (mma f16.f16.f16.f16 -> fewer RF ports),
// promoted to FP32 master accumulators once per 64-k chunk.
// smem halves: A 3x(128x72)=27648, B 3x9216=27648 -> 110,592 B per CTA.
// ---------------------------------------------------------------------------
#define P_AS 9216
#define P_BS 9216
#define P_B_BASE (3 * P_AS)
#define P_SMEM_H (3 * P_AS + 3 * P_BS)

__global__ void __launch_bounds__(128, 2)
prop_kernel(float* __restrict__ out)
{
    extern __shared__ __half smh[];
    const unsigned sbase = smem_u32(smh);

    const int cs  = blockIdx.x & 1;          // c-strip (128)
    const int jt  = blockIdx.x >> 1;         // j-tile (128)
    const int b   = blockIdx.y;
    const int j0  = jt * TI;
    const int tid = threadIdx.x;
    const int wid = tid >> 5;
    const int lane = tid & 31;

    const int wc = wid & 1;    // c-half (64 rows)
    const int wj = wid >> 1;   // j-half (64 cols)
    const unsigned lrow = (unsigned)(lane & 15);
    const unsigned lk8  = (unsigned)((lane >> 4) * 8);
    const unsigned qrow = (unsigned)((((lane >> 3) & 1) * 8) + (lane & 7));

    const __half* t_b = g_t_h + (size_t)b * C * HW;
    const __half* Qb  = g_Q + ((size_t)b * HW * HW);

    auto issue = [&](int ck) {
        const int k0 = ck * 64;
        const int kb = k0 >> 7;
        const int s  = ck % 3;
        const unsigned a_o = (unsigned)(s * P_AS);
        const unsigned b_o = (unsigned)(P_B_BASE + s * P_BS);
        #pragma unroll
        for (int r = 0; r < 8; ++r) {
            int f = r * 128 + tid;
            int row = f >> 3, ch = f & 7;
            cpa16(sbase + (a_o + (unsigned)(row * 72 + ch * 8)) * 2,
                  t_b + (size_t)(cs * 128 + row) * HW + k0 + ch * 8);
        }
        if (kb >= jt) {
            #pragma unroll
            for (int r = 0; r < 8; ++r) {
                int f = r * 128 + tid;
                int row = f >> 4, ch = f & 15;
                cpa16(sbase + (b_o + (unsigned)(row * 136 + ch * 8)) * 2,
                      Qb + (size_t)(k0 + row) * HW + j0 + ch * 8);
            }
        } else {
            #pragma unroll
            for (int r = 0; r < 8; ++r) {
                int f = r * 128 + tid;
                int row = f >> 3, ch = f & 7;
                cpa16(sbase + (b_o + (unsigned)(row * 72 + ch * 8)) * 2,
                      Qb + (size_t)(j0 + row) * HW + k0 + ch * 8);
            }
        }
        cpa_commit();
    };

    issue(0);
    issue(1);

    float acc[4][8][4];
    #pragma unroll
    for (int s = 0; s < 4; ++s)
        #pragma unroll
        for (int t = 0; t < 8; ++t)
            #pragma unroll
            for (int r = 0; r < 4; ++r) acc[s][t][r] = 0.f;

    const unsigned aAinv = sbase + ((unsigned)((wc * 64 + lrow) * 72) + lk8) * 2;

    const int NCK = HW / 64;
    for (int ck = 0; ck < NCK; ++ck) {
        if (ck + 2 < NCK) {
            issue(ck + 2);
            asm volatile("cp.async.wait_group 2;" ::: "memory");
        } else if (ck + 1 < NCK) {
            asm volatile("cp.async.wait_group 1;" ::: "memory");
        } else {
            asm volatile("cp.async.wait_group 0;" ::: "memory");
        }
        __syncthreads();   // chunk ck resident for all warps

        const int k0 = ck * 64;
        const int kb = k0 >> 7;
        const int sb = ck % 3;
        const unsigned a_o = (unsigned)(sb * P_AS);
        const unsigned b_o = (unsigned)(P_B_BASE + sb * P_BS);
        const unsigned aA = aAinv + a_o * 2;

        // fp16 chunk accumulators (zeroed per chunk)
        unsigned hacc[4][8][2];
        #pragma unroll
        for (int s = 0; s < 4; ++s)
            #pragma unroll
            for (int t = 0; t < 8; ++t) { hacc[s][t][0] = 0u; hacc[s][t][1] = 0u; }

        if (kb >= jt) {
            #pragma unroll
            for (int kk = 0; kk < 4; ++kk) {
                unsigned aa[4][4];
                #pragma unroll
                for (int s = 0; s < 4; ++s)
                    ldsm_x4(aa[s], aA + (unsigned)(s * 16 * 72 * 2) + kk * 32);
                #pragma unroll
                for (int tp = 0; tp < 4; ++tp) {
                    unsigned bq[4];
                    ldsm_x4t(bq, sbase + (b_o + (unsigned)((kk * 16 + qrow) * 136 +
                                                           wj * 64 + tp * 16) + lk8) * 2);
                    #pragma unroll
                    for (int s = 0; s < 4; ++s) {
                        mma_h16(hacc[s][tp * 2 + 0], aa[s], bq[0], bq[1]);
                        mma_h16(hacc[s][tp * 2 + 1], aa[s], bq[2], bq[3]);
                    }
                }
            }
        } else {
            #pragma unroll
            for (int kk = 0; kk < 4; ++kk) {
                unsigned aa[4][4];
                #pragma unroll
                for (int s = 0; s < 4; ++s)
                    ldsm_x4(aa[s], aA + (unsigned)(s * 16 * 72 * 2) + kk * 32);
                #pragma unroll
                for (int tt = 0; tt < 4; ++tt) {
                    unsigned bb[4];
                    ldsm_x4(bb, sbase + (b_o + (unsigned)((wj * 64 + tt * 16 + lrow) * 72) +
                                         (unsigned)(kk * 16) + lk8) * 2);
                    #pragma unroll
                    for (int s = 0; s < 4; ++s) {
                        mma_h16(hacc[s][tt * 2 + 0], aa[s], bb[0], bb[2]);
                        mma_h16(hacc[s][tt * 2 + 1], aa[s], bb[1], bb[3]);
                    }
                }
            }
        }

        // promote fp16 chunk sums to fp32 master accumulators
        #pragma unroll
        for (int s = 0; s < 4; ++s)
            #pragma unroll
            for (int t = 0; t < 8; ++t) {
                float2 lo = __half22float2(*reinterpret_cast<__half2*>(&hacc[s][t][0]));
                float2 hi = __half22float2(*reinterpret_cast<__half2*>(&hacc[s][t][1]));
                acc[s][t][0] += lo.x;
                acc[s][t][1] += lo.y;
                acc[s][t][2] += hi.x;
                acc[s][t][3] += hi.y;
            }

        __syncthreads();   // buffer sb free before refill
    }

    float* ob = out + (size_t)b * C * HW;
    #pragma unroll
    for (int s = 0; s < 4; ++s) {
        const int c0 = cs * 128 + wc * 64 + s * 16 + (lane >> 2);
        #pragma unroll
        for (int t = 0; t < 8; ++t) {
            const int col = j0 + wj * 64 + t * 8 + (lane & 3) * 2;
            *reinterpret_cast<float2*>(ob + (size_t)c0 * HW + col) =
                make_float2(acc[s][t][0], acc[s][t][1]);
            *reinterpret_cast<float2*>(ob + (size_t)(c0 + 8) * HW + col) =
                make_float2(acc[s][t][2], acc[s][t][3]);
        }
    }
}

// ---------------------------------------------------------------------------
extern "C" void kernel_launch(void* const* d_in, const int* in_sizes, int n_in,
                              void* d_out, int out_size)
{
    const float* x    = (const float*)d_in[0];
    const float* W    = (const float*)d_in[1];
    const float* bias = (const float*)d_in[2];
    float* out        = (float*)d_out;

    const int PREP_SMEM = (C * 68 + 64) * 4;
    const int TG_SMEM   = TG_SMEM_H * 2;
    const int Q_SMEM    = Q_SMEM_H * 2;      // 108,544 B -> 2 CTAs/SM
    const int P_SMEM    = P_SMEM_H * 2;      // 110,592 B -> 2 CTAs/SM (128 thr)

    cudaFuncSetAttribute(prep_kernel,   cudaFuncAttributeMaxDynamicSharedMemorySize, PREP_SMEM);
    cudaFuncSetAttribute(tgemm_kernel,  cudaFuncAttributeMaxDynamicSharedMemorySize, TG_SMEM);
    cudaFuncSetAttribute(qbuild_kernel, cudaFuncAttributeMaxDynamicSharedMemorySize, Q_SMEM);
    cudaFuncSetAttribute(prop_kernel,   cudaFuncAttributeMaxDynamicSharedMemorySize, P_SMEM);

    conv_w_kernel<<<64, 256>>>(W);

    dim3 g1(HW / PT, BATCH);
    prep_kernel<<<g1, 256, PREP_SMEM>>>(x);

    dim3 gt(HW / 128, BATCH);
    tgemm_kernel<<<gt, 256, TG_SMEM>>>(bias);

    dim3 gq(NPAIR, BATCH);
    qbuild_kernel<<<gq, 256, Q_SMEM>>>();

    dim3 gp(2 * NTI, BATCH);
    prop_kernel<<<gp, 128, P_SMEM>>>(out);
}

// round 15
// speedup vs baseline: 1.0836x; 1.0836x over previous
#include <cuda_runtime.h>
#include <cuda_fp16.h>

#define BATCH 8
#define C 256
#define HW 4096
#define PT 64
#define TI 128
#define NTI (HW / TI)                // 32
#define NPAIR (NTI * (NTI + 1) / 2)  // 528

// Global scratch
__device__ __half g_xnT_h[(size_t)BATCH * HW * C];  // normalized, pixel-major (p, c)
__device__ float  g_norm [(size_t)BATCH * HW];      // channel L2 norm per pixel
__device__ __half g_t_h  [(size_t)BATCH * C * HW];  // t = Wx+b, c-major (c, p)
__device__ __half g_W_h  [C * C];                   // W fp16
__device__ __half g_Q    [(size_t)BATCH * HW * HW]; // Q = S^2, lower-block-triangle only

__device__ __forceinline__ unsigned smem_u32(const void* p) {
    unsigned a;
    asm("{ .reg .u64 t; cvta.to.shared.u64 t, %1; cvt.u32.u64 %0, t; }" : "=r"(a) : "l"(p));
    return a;
}
__device__ __forceinline__ void cpa16(unsigned dst, const void* src) {
    asm volatile("cp.async.cg.shared.global [%0], [%1], 16;" :: "r"(dst), "l"(src) : "memory");
}
__device__ __forceinline__ void cpa_commit() {
    asm volatile("cp.async.commit_group;" ::: "memory");
}
__device__ __forceinline__ void ldsm_x4(unsigned* r, unsigned addr) {
    asm volatile("ldmatrix.sync.aligned.m8n8.x4.shared.b16 {%0,%1,%2,%3}, [%4];"
                 : "=r"(r[0]), "=r"(r[1]), "=r"(r[2]), "=r"(r[3]) : "r"(addr));
}
__device__ __forceinline__ void ldsm_x4t(unsigned* r, unsigned addr) {
    asm volatile("ldmatrix.sync.aligned.m8n8.x4.trans.shared.b16 {%0,%1,%2,%3}, [%4];"
                 : "=r"(r[0]), "=r"(r[1]), "=r"(r[2]), "=r"(r[3]) : "r"(addr));
}
__device__ __forceinline__ void mma_f16(float d[4], const unsigned a[4], unsigned b0, unsigned b1) {
    asm volatile(
        "mma.sync.aligned.m16n8k16.row.col.f32.f16.f16.f32 "
        "{%0,%1,%2,%3}, {%4,%5,%6,%7}, {%8,%9}, {%0,%1,%2,%3};"
        : "+f"(d[0]), "+f"(d[1]), "+f"(d[2]), "+f"(d[3])
        : "r"(a[0]), "r"(a[1]), "r"(a[2]), "r"(a[3]), "r"(b0), "r"(b1));
}
__device__ __forceinline__ unsigned pack_h2(float a, float b) {
    __half2 h = __floats2half2_rn(a, b);
    return *reinterpret_cast<unsigned*>(&h);
}

// ---------------------------------------------------------------------------
__global__ void conv_w_kernel(const float* __restrict__ W) {
    int i = (blockIdx.x * 256 + threadIdx.x) * 4;
    float4 v = *reinterpret_cast<const float4*>(W + i);
    uint2 u;
    u.x = pack_h2(v.x, v.y);
    u.y = pack_h2(v.z, v.w);
    *reinterpret_cast<uint2*>(g_W_h + i) = u;
}

// ---------------------------------------------------------------------------
// Prep: invn + write xnT_h (normalized, fp16) + g_norm (fp32)
// ---------------------------------------------------------------------------
__global__ void __launch_bounds__(256, 1)
prep_kernel(const float* __restrict__ x)
{
    extern __shared__ float sm[];
    float* xs   = sm;                  // C * 68
    float* invn = xs + C * 68;         // 64

    const int p0  = blockIdx.x * PT;
    const int b   = blockIdx.y;
    const int tid = threadIdx.x;
    const float* xb = x + (size_t)b * C * HW;

    #pragma unroll
    for (int r = 0; r < 16; ++r) {
        int f4 = r * 256 + tid;
        int c  = f4 >> 4;
        int kq = f4 & 15;
        float4 v = *reinterpret_cast<const float4*>(xb + (size_t)c * HW + p0 + kq * 4);
        *reinterpret_cast<float4*>(xs + c * 68 + kq * 4) = v;
    }
    __syncthreads();

    if (tid < 64) {
        float s = 0.f;
        #pragma unroll 8
        for (int c = 0; c < C; ++c) { float v = xs[c * 68 + tid]; s += v * v; }
        float nrm = fmaxf(sqrtf(s), 1e-12f);
        g_norm[(size_t)b * HW + p0 + tid] = nrm;
        invn[tid] = 1.0f / nrm;
    }
    __syncthreads();

    {
        int p   = tid & 63;
        int grp = tid >> 6;
        float inv = invn[p];
        __half* dn = g_xnT_h + ((size_t)b * HW + p0 + p) * C;
        #pragma unroll
        for (int cc = 0; cc < 16; ++cc) {
            int c = grp * 64 + cc * 4;
            uint2 un;
            un.x = pack_h2(xs[(c + 0) * 68 + p] * inv, xs[(c + 1) * 68 + p] * inv);
            un.y = pack_h2(xs[(c + 2) * 68 + p] * inv, xs[(c + 3) * 68 + p] * inv);
            *reinterpret_cast<uint2*>(dn + c) = un;
        }
    }
}

// ---------------------------------------------------------------------------
// tgemm: t[c][p] = norm[p] * (W @ xn)[c][p] + bias[c]
// ---------------------------------------------------------------------------
#define TG_WS 18432
#define TG_XS 9216
#define TG_SMEM_H (2 * TG_WS + 2 * TG_XS)

__global__ void __launch_bounds__(256, 1)
tgemm_kernel(const float* __restrict__ bias)
{
    extern __shared__ __half smh[];
    const unsigned sbase = smem_u32(smh);

    const int p0  = blockIdx.x * 128;
    const int b   = blockIdx.y;
    const int tid = threadIdx.x;
    const int wid = tid >> 5;
    const int lane = tid & 31;
    const int wm = wid & 3;
    const int wn = wid >> 2;
    const unsigned lrow = (unsigned)(lane & 15);
    const unsigned lk8  = (unsigned)((lane >> 4) * 8);

    const __half* xn_b = g_xnT_h + (size_t)b * HW * C;

    auto issue = [&](int ck) {
        const int k0 = ck * 64;
        const unsigned ws_o = (unsigned)((ck & 1) * TG_WS);
        const unsigned xs_o = (unsigned)(2 * TG_WS + (ck & 1) * TG_XS);
        #pragma unroll
        for (int r = 0; r < 8; ++r) {
            int f = r * 256 + tid;
            int c = f >> 3, ch = f & 7;
            cpa16(sbase + (ws_o + (unsigned)(c * 72 + ch * 8)) * 2,
                  g_W_h + (size_t)c * C + k0 + ch * 8);
        }
        #pragma unroll
        for (int r = 0; r < 4; ++r) {
            int f = r * 256 + tid;
            int p = f >> 3, ch = f & 7;
            cpa16(sbase + (xs_o + (unsigned)(p * 72 + ch * 8)) * 2,
                  xn_b + (size_t)(p0 + p) * C + k0 + ch * 8);
        }
        cpa_commit();
    };

    issue(0);

    float acc[4][8][4];
    #pragma unroll
    for (int m = 0; m < 4; ++m)
        #pragma unroll
        for (int t = 0; t < 8; ++t)
            #pragma unroll
            for (int r = 0; r < 4; ++r) acc[m][t][r] = 0.f;

    for (int ck = 0; ck < 4; ++ck) {
        if (ck + 1 < 4) {
            issue(ck + 1);
            asm volatile("cp.async.wait_group 1;" ::: "memory");
        } else {
            asm volatile("cp.async.wait_group 0;" ::: "memory");
        }
        __syncthreads();
        const unsigned ws_o = (unsigned)((ck & 1) * TG_WS);
        const unsigned xs_o = (unsigned)(2 * TG_WS + (ck & 1) * TG_XS);

        const unsigned aA = sbase + (ws_o + (unsigned)((wm * 64 + lrow) * 72) + lk8) * 2;
        const unsigned aB = sbase + (xs_o + (unsigned)((wn * 64 + lrow) * 72) + lk8) * 2;
        #pragma unroll
        for (int kk = 0; kk < 4; ++kk) {
            unsigned a[4][4], bb[4][4];
            #pragma unroll
            for (int m = 0; m < 4; ++m)
                ldsm_x4(a[m], aA + (unsigned)(m * 16 * 72 * 2) + kk * 32);
            #pragma unroll
            for (int n = 0; n < 4; ++n)
                ldsm_x4(bb[n], aB + (unsigned)(n * 16 * 72 * 2) + kk * 32);
            #pragma unroll
            for (int m = 0; m < 4; ++m)
                #pragma unroll
                for (int n = 0; n < 4; ++n) {
                    mma_f16(acc[m][n * 2 + 0], a[m], bb[n][0], bb[n][2]);
                    mma_f16(acc[m][n * 2 + 1], a[m], bb[n][1], bb[n][3]);
                }
        }
        __syncthreads();
    }

    __half* tb = g_t_h + (size_t)b * C * HW;
    const float* nb = g_norm + (size_t)b * HW;
    #pragma unroll
    for (int m = 0; m < 4; ++m) {
        const int c0 = wm * 64 + m * 16 + (lane >> 2);
        const float bo0 = __ldg(bias + c0);
        const float bo1 = __ldg(bias + c0 + 8);
        #pragma unroll
        for (int t = 0; t < 8; ++t) {
            const int p = p0 + wn * 64 + t * 8 + (lane & 3) * 2;
            float2 n2 = *reinterpret_cast<const float2*>(nb + p);
            *reinterpret_cast<unsigned*>(tb + (size_t)c0 * HW + p) =
                pack_h2(acc[m][t][0] * n2.x + bo0, acc[m][t][1] * n2.y + bo0);
            *reinterpret_cast<unsigned*>(tb + (size_t)(c0 + 8) * HW + p) =
                pack_h2(acc[m][t][2] * n2.x + bo1, acc[m][t][3] * n2.y + bo1);
        }
    }
}

// ---------------------------------------------------------------------------
// qbuild: per (pair, b): S = Xn_i Xn_j^T (128x128, K=256 in four 64-chunks,
//         double-buffered), Q = S^2 -> g_Q[i][j].  Pairs with ti >= tj.
// smem halves: xi 2x(128x72), xj 2x(128x72), qs 128x136 = 108,544 B -> 2 CTAs
// ---------------------------------------------------------------------------
#define QB_XI0 0
#define QB_XI1 9216
#define QB_XJ0 18432
#define QB_XJ1 27648
#define QB_QS  36864
#define Q_SMEM_H 54272

__global__ void __launch_bounds__(256, 2)
qbuild_kernel()
{
    extern __shared__ __half smh[];
    const unsigned sbase = smem_u32(smh);

    const int p   = blockIdx.x;
    const int b   = blockIdx.y;
    const int tid = threadIdx.x;
    const int wid = tid >> 5;
    const int lane = tid & 31;

    int ti = (int)((sqrtf(8.f * (float)p + 1.f) - 1.f) * 0.5f);
    while ((ti + 1) * (ti + 2) / 2 <= p) ++ti;
    while (ti * (ti + 1) / 2 > p) --ti;
    const int tj = p - ti * (ti + 1) / 2;
    const int i0 = ti * TI;
    const int j0 = tj * TI;

    const __half* xnT_b = g_xnT_h + (size_t)b * HW * C;

    const int wm = wid & 3;    // i-strip (32 rows)
    const int wn = wid >> 2;   // j-half (64 cols)
    const unsigned lrow = (unsigned)(lane & 15);
    const unsigned lk8  = (unsigned)((lane >> 4) * 8);

    auto issue = [&](int kc) {
        const int kb = kc * 64;
        const unsigned xi_o = (unsigned)((kc & 1) ? QB_XI1 : QB_XI0);
        const unsigned xj_o = (unsigned)((kc & 1) ? QB_XJ1 : QB_XJ0);
        #pragma unroll
        for (int r = 0; r < 4; ++r) {
            int f = r * 256 + tid;
            int row = f >> 3, ch = f & 7;
            cpa16(sbase + (xi_o + (unsigned)(row * 72 + ch * 8)) * 2,
                  xnT_b + (size_t)(i0 + row) * C + kb + ch * 8);
            cpa16(sbase + (xj_o + (unsigned)(row * 72 + ch * 8)) * 2,
                  xnT_b + (size_t)(j0 + row) * C + kb + ch * 8);
        }
        cpa_commit();
    };

    issue(0);

    float d[2][8][4];
    #pragma unroll
    for (int m = 0; m < 2; ++m)
        #pragma unroll
        for (int t = 0; t < 8; ++t)
            #pragma unroll
            for (int r = 0; r < 4; ++r) d[m][t][r] = 0.f;

    for (int kc = 0; kc < 4; ++kc) {
        if (kc + 1 < 4) {
            issue(kc + 1);
            asm volatile("cp.async.wait_group 1;" ::: "memory");
        } else {
            asm volatile("cp.async.wait_group 0;" ::: "memory");
        }
        __syncthreads();

        const unsigned xi_o = (unsigned)((kc & 1) ? QB_XI1 : QB_XI0);
        const unsigned xj_o = (unsigned)((kc & 1) ? QB_XJ1 : QB_XJ0);
        const unsigned aA = sbase + (xi_o + (unsigned)((wm * 32 + lrow) * 72) + lk8) * 2;
        const unsigned aB = sbase + (xj_o + (unsigned)((wn * 64 + lrow) * 72) + lk8) * 2;

        #pragma unroll
        for (int kk = 0; kk < 4; ++kk) {
            unsigned a[2][4];
            ldsm_x4(a[0], aA + kk * 32);
            ldsm_x4(a[1], aA + 16 * 72 * 2 + kk * 32);
            #pragma unroll
            for (int tt = 0; tt < 4; ++tt) {
                unsigned bb[4];
                ldsm_x4(bb, aB + (unsigned)(tt * 16 * 72 * 2) + kk * 32);
                #pragma unroll
                for (int m = 0; m < 2; ++m) {
                    mma_f16(d[m][tt * 2 + 0], a[m], bb[0], bb[2]);
                    mma_f16(d[m][tt * 2 + 1], a[m], bb[1], bb[3]);
                }
            }
        }
        __syncthreads();
    }

    {
        __half* qsm = smh + QB_QS;
        #pragma unroll
        for (int m = 0; m < 2; ++m) {
            const int r0 = wm * 32 + m * 16 + (lane >> 2);
            #pragma unroll
            for (int t = 0; t < 8; ++t) {
                const int col = wn * 64 + t * 8 + (lane & 3) * 2;
                *reinterpret_cast<unsigned*>(qsm + r0 * 136 + col) =
                    pack_h2(d[m][t][0] * d[m][t][0], d[m][t][1] * d[m][t][1]);
                *reinterpret_cast<unsigned*>(qsm + (r0 + 8) * 136 + col) =
                    pack_h2(d[m][t][2] * d[m][t][2], d[m][t][3] * d[m][t][3]);
            }
        }
    }
    __syncthreads();

    __half* Qb = g_Q + ((size_t)b * HW * HW);
    #pragma unroll
    for (int rr = 0; rr < 16; ++rr) {
        const int r = wid * 16 + rr;
        uint2 v = *reinterpret_cast<const uint2*>(smh + QB_QS + r * 136 + lane * 4);
        *reinterpret_cast<uint2*>(Qb + (size_t)(i0 + r) * HW + j0 + lane * 4) = v;
    }
}

// ---------------------------------------------------------------------------
// propagate: out[b][c][j] = sum_k t[c][k] * Q_sym[k][j]
// CTA: 128 c x 128 j, 128 threads (2x2 grid of 64x64 warp tiles), 3 CTAs/SM,
// K=4096 in 64-chunks, TWO-stage cp.async pipeline (73,728 B smem/CTA).
// 3 CTAs/SM -> 444 concurrent CTAs, grid 512 = 1.15 waves (tail fix).
// ---------------------------------------------------------------------------
#define P_AS 9216
#define P_BS 9216
#define P_B_BASE (2 * P_AS)
#define P_SMEM_H (2 * P_AS + 2 * P_BS)

__global__ void __launch_bounds__(128, 3)
prop_kernel(float* __restrict__ out)
{
    extern __shared__ __half smh[];
    const unsigned sbase = smem_u32(smh);

    const int cs  = blockIdx.x & 1;          // c-strip (128)
    const int jt  = blockIdx.x >> 1;         // j-tile (128)
    const int b   = blockIdx.y;
    const int j0  = jt * TI;
    const int tid = threadIdx.x;
    const int wid = tid >> 5;
    const int lane = tid & 31;

    const int wc = wid & 1;    // c-half (64 rows)
    const int wj = wid >> 1;   // j-half (64 cols)
    const unsigned lrow = (unsigned)(lane & 15);
    const unsigned lk8  = (unsigned)((lane >> 4) * 8);
    const unsigned qrow = (unsigned)((((lane >> 3) & 1) * 8) + (lane & 7));

    const __half* t_b = g_t_h + (size_t)b * C * HW;
    const __half* Qb  = g_Q + ((size_t)b * HW * HW);

    auto issue = [&](int ck) {
        const int k0 = ck * 64;
        const int kb = k0 >> 7;
        const unsigned a_o = (unsigned)((ck & 1) * P_AS);
        const unsigned b_o = (unsigned)(P_B_BASE + (ck & 1) * P_BS);
        #pragma unroll
        for (int r = 0; r < 8; ++r) {
            int f = r * 128 + tid;
            int row = f >> 3, ch = f & 7;
            cpa16(sbase + (a_o + (unsigned)(row * 72 + ch * 8)) * 2,
                  t_b + (size_t)(cs * 128 + row) * HW + k0 + ch * 8);
        }
        if (kb >= jt) {
            // k-major tile: 64 rows(k) x 128 cols(j), stride 136
            #pragma unroll
            for (int r = 0; r < 8; ++r) {
                int f = r * 128 + tid;
                int row = f >> 4, ch = f & 15;
                cpa16(sbase + (b_o + (unsigned)(row * 136 + ch * 8)) * 2,
                      Qb + (size_t)(k0 + row) * HW + j0 + ch * 8);
            }
        } else {
            // j-major tile: 128 rows(j) x 64 cols(k), stride 72
            #pragma unroll
            for (int r = 0; r < 8; ++r) {
                int f = r * 128 + tid;
                int row = f >> 3, ch = f & 7;
                cpa16(sbase + (b_o + (unsigned)(row * 72 + ch * 8)) * 2,
                      Qb + (size_t)(j0 + row) * HW + k0 + ch * 8);
            }
        }
        cpa_commit();
    };

    issue(0);

    float acc[4][8][4];
    #pragma unroll
    for (int s = 0; s < 4; ++s)
        #pragma unroll
        for (int t = 0; t < 8; ++t)
            #pragma unroll
            for (int r = 0; r < 4; ++r) acc[s][t][r] = 0.f;

    const unsigned aAinv = sbase + ((unsigned)((wc * 64 + lrow) * 72) + lk8) * 2;

    const int NCK = HW / 64;
    for (int ck = 0; ck < NCK; ++ck) {
        if (ck + 1 < NCK) {
            issue(ck + 1);
            asm volatile("cp.async.wait_group 1;" ::: "memory");
        } else {
            asm volatile("cp.async.wait_group 0;" ::: "memory");
        }
        __syncthreads();   // chunk ck resident; buffer (ck+1)&1 free was ensured last iter

        const int k0 = ck * 64;
        const int kb = k0 >> 7;
        const unsigned a_o = (unsigned)((ck & 1) * P_AS);
        const unsigned b_o = (unsigned)(P_B_BASE + (ck & 1) * P_BS);
        const unsigned aA = aAinv + a_o * 2;

        if (kb >= jt) {
            #pragma unroll
            for (int kk = 0; kk < 4; ++kk) {
                unsigned aa[4][4];
                #pragma unroll
                for (int s = 0; s < 4; ++s)
                    ldsm_x4(aa[s], aA + (unsigned)(s * 16 * 72 * 2) + kk * 32);
                #pragma unroll
                for (int tp = 0; tp < 4; ++tp) {
                    unsigned bq[4];
                    ldsm_x4t(bq, sbase + (b_o + (unsigned)((kk * 16 + qrow) * 136 +
                                                           wj * 64 + tp * 16) + lk8) * 2);
                    #pragma unroll
                    for (int s = 0; s < 4; ++s) {
                        mma_f16(acc[s][tp * 2 + 0], aa[s], bq[0], bq[1]);
                        mma_f16(acc[s][tp * 2 + 1], aa[s], bq[2], bq[3]);
                    }
                }
            }
        } else {
            #pragma unroll
            for (int kk = 0; kk < 4; ++kk) {
                unsigned aa[4][4];
                #pragma unroll
                for (int s = 0; s < 4; ++s)
                    ldsm_x4(aa[s], aA + (unsigned)(s * 16 * 72 * 2) + kk * 32);
                #pragma unroll
                for (int tt = 0; tt < 4; ++tt) {
                    unsigned bb[4];
                    ldsm_x4(bb, sbase + (b_o + (unsigned)((wj * 64 + tt * 16 + lrow) * 72) +
                                         (unsigned)(kk * 16) + lk8) * 2);
                    #pragma unroll
                    for (int s = 0; s < 4; ++s) {
                        mma_f16(acc[s][tt * 2 + 0], aa[s], bb[0], bb[2]);
                        mma_f16(acc[s][tt * 2 + 1], aa[s], bb[1], bb[3]);
                    }
                }
            }
        }
        __syncthreads();   // buffer ck&1 free before refill in next iter
    }

    float* ob = out + (size_t)b * C * HW;
    #pragma unroll
    for (int s = 0; s < 4; ++s) {
        const int c0 = cs * 128 + wc * 64 + s * 16 + (lane >> 2);
        #pragma unroll
        for (int t = 0; t < 8; ++t) {
            const int col = j0 + wj * 64 + t * 8 + (lane & 3) * 2;
            *reinterpret_cast<float2*>(ob + (size_t)c0 * HW + col) =
                make_float2(acc[s][t][0], acc[s][t][1]);
            *reinterpret_cast<float2*>(ob + (size_t)(c0 + 8) * HW + col) =
                make_float2(acc[s][t][2], acc[s][t][3]);
        }
    }
}

// ---------------------------------------------------------------------------
extern "C" void kernel_launch(void* const* d_in, const int* in_sizes, int n_in,
                              void* d_out, int out_size)
{
    const float* x    = (const float*)d_in[0];
    const float* W    = (const float*)d_in[1];
    const float* bias = (const float*)d_in[2];
    float* out        = (float*)d_out;

    const int PREP_SMEM = (C * 68 + 64) * 4;
    const int TG_SMEM   = TG_SMEM_H * 2;
    const int Q_SMEM    = Q_SMEM_H * 2;      // 108,544 B -> 2 CTAs/SM
    const int P_SMEM    = P_SMEM_H * 2;      // 73,728 B  -> 3 CTAs/SM (128 thr)

    cudaFuncSetAttribute(prep_kernel,   cudaFuncAttributeMaxDynamicSharedMemorySize, PREP_SMEM);
    cudaFuncSetAttribute(tgemm_kernel,  cudaFuncAttributeMaxDynamicSharedMemorySize, TG_SMEM);
    cudaFuncSetAttribute(qbuild_kernel, cudaFuncAttributeMaxDynamicSharedMemorySize, Q_SMEM);
    cudaFuncSetAttribute(prop_kernel,   cudaFuncAttributeMaxDynamicSharedMemorySize, P_SMEM);

    conv_w_kernel<<<64, 256>>>(W);

    dim3 g1(HW / PT, BATCH);
    prep_kernel<<<g1, 256, PREP_SMEM>>>(x);

    dim3 gt(HW / 128, BATCH);
    tgemm_kernel<<<gt, 256, TG_SMEM>>>(bias);

    dim3 gq(NPAIR, BATCH);
    qbuild_kernel<<<gq, 256, Q_SMEM>>>();

    dim3 gp(2 * NTI, BATCH);
    prop_kernel<<<gp, 128, P_SMEM>>>(out);
}

// round 17
// speedup vs baseline: 1.1436x; 1.0554x over previous
#include <cuda_runtime.h>
#include <cuda_fp16.h>

#define BATCH 8
#define C 256
#define HW 4096
#define PT 64
#define TI 128
#define NTI (HW / TI)                // 32
#define NPAIR (NTI * (NTI + 1) / 2)  // 528

// Global scratch
__device__ __half g_xnT_h[(size_t)BATCH * HW * C];  // normalized, pixel-major (p, c)
__device__ float  g_norm [(size_t)BATCH * HW];      // channel L2 norm per pixel
__device__ __half g_t_h  [(size_t)BATCH * C * HW];  // t = Wx+b, c-major (c, p)
__device__ __half g_W_h  [C * C];                   // W fp16
__device__ __half g_Q    [(size_t)BATCH * HW * HW]; // Q = S^2, lower-block-triangle only

__device__ __forceinline__ unsigned smem_u32(const void* p) {
    unsigned a;
    asm("{ .reg .u64 t; cvta.to.shared.u64 t, %1; cvt.u32.u64 %0, t; }" : "=r"(a) : "l"(p));
    return a;
}
__device__ __forceinline__ void cpa16(unsigned dst, const void* src) {
    asm volatile("cp.async.cg.shared.global [%0], [%1], 16;" :: "r"(dst), "l"(src) : "memory");
}
__device__ __forceinline__ void cpa_commit() {
    asm volatile("cp.async.commit_group;" ::: "memory");
}
__device__ __forceinline__ void ldsm_x4(unsigned* r, unsigned addr) {
    asm volatile("ldmatrix.sync.aligned.m8n8.x4.shared.b16 {%0,%1,%2,%3}, [%4];"
                 : "=r"(r[0]), "=r"(r[1]), "=r"(r[2]), "=r"(r[3]) : "r"(addr));
}
__device__ __forceinline__ void ldsm_x4t(unsigned* r, unsigned addr) {
    asm volatile("ldmatrix.sync.aligned.m8n8.x4.trans.shared.b16 {%0,%1,%2,%3}, [%4];"
                 : "=r"(r[0]), "=r"(r[1]), "=r"(r[2]), "=r"(r[3]) : "r"(addr));
}
__device__ __forceinline__ void mma_f16(float d[4], const unsigned a[4], unsigned b0, unsigned b1) {
    asm volatile(
        "mma.sync.aligned.m16n8k16.row.col.f32.f16.f16.f32 "
        "{%0,%1,%2,%3}, {%4,%5,%6,%7}, {%8,%9}, {%0,%1,%2,%3};"
        : "+f"(d[0]), "+f"(d[1]), "+f"(d[2]), "+f"(d[3])
        : "r"(a[0]), "r"(a[1]), "r"(a[2]), "r"(a[3]), "r"(b0), "r"(b1));
}
__device__ __forceinline__ unsigned pack_h2(float a, float b) {
    __half2 h = __floats2half2_rn(a, b);
    return *reinterpret_cast<unsigned*>(&h);
}

// ---------------------------------------------------------------------------
__global__ void conv_w_kernel(const float* __restrict__ W) {
    int i = (blockIdx.x * 256 + threadIdx.x) * 4;
    float4 v = *reinterpret_cast<const float4*>(W + i);
    uint2 u;
    u.x = pack_h2(v.x, v.y);
    u.y = pack_h2(v.z, v.w);
    *reinterpret_cast<uint2*>(g_W_h + i) = u;
}

// ---------------------------------------------------------------------------
// Prep: invn + write xnT_h (normalized, fp16) + g_norm (fp32)
// ---------------------------------------------------------------------------
__global__ void __launch_bounds__(256, 1)
prep_kernel(const float* __restrict__ x)
{
    extern __shared__ float sm[];
    float* xs   = sm;                  // C * 68
    float* invn = xs + C * 68;         // 64

    const int p0  = blockIdx.x * PT;
    const int b   = blockIdx.y;
    const int tid = threadIdx.x;
    const float* xb = x + (size_t)b * C * HW;

    #pragma unroll
    for (int r = 0; r < 16; ++r) {
        int f4 = r * 256 + tid;
        int c  = f4 >> 4;
        int kq = f4 & 15;
        float4 v = *reinterpret_cast<const float4*>(xb + (size_t)c * HW + p0 + kq * 4);
        *reinterpret_cast<float4*>(xs + c * 68 + kq * 4) = v;
    }
    __syncthreads();

    if (tid < 64) {
        float s = 0.f;
        #pragma unroll 8
        for (int c = 0; c < C; ++c) { float v = xs[c * 68 + tid]; s += v * v; }
        float nrm = fmaxf(sqrtf(s), 1e-12f);
        g_norm[(size_t)b * HW + p0 + tid] = nrm;
        invn[tid] = 1.0f / nrm;
    }
    __syncthreads();

    {
        int p   = tid & 63;
        int grp = tid >> 6;
        float inv = invn[p];
        __half* dn = g_xnT_h + ((size_t)b * HW + p0 + p) * C;
        #pragma unroll
        for (int cc = 0; cc < 16; ++cc) {
            int c = grp * 64 + cc * 4;
            uint2 un;
            un.x = pack_h2(xs[(c + 0) * 68 + p] * inv, xs[(c + 1) * 68 + p] * inv);
            un.y = pack_h2(xs[(c + 2) * 68 + p] * inv, xs[(c + 3) * 68 + p] * inv);
            *reinterpret_cast<uint2*>(dn + c) = un;
        }
    }
}

// ---------------------------------------------------------------------------
// tgemm: t[c][p] = norm[p] * (W @ xn)[c][p] + bias[c]
// ---------------------------------------------------------------------------
#define TG_WS 18432
#define TG_XS 9216
#define TG_SMEM_H (2 * TG_WS + 2 * TG_XS)

__global__ void __launch_bounds__(256, 1)
tgemm_kernel(const float* __restrict__ bias)
{
    extern __shared__ __half smh[];
    const unsigned sbase = smem_u32(smh);

    const int p0  = blockIdx.x * 128;
    const int b   = blockIdx.y;
    const int tid = threadIdx.x;
    const int wid = tid >> 5;
    const int lane = tid & 31;
    const int wm = wid & 3;
    const int wn = wid >> 2;
    const unsigned lrow = (unsigned)(lane & 15);
    const unsigned lk8  = (unsigned)((lane >> 4) * 8);

    const __half* xn_b = g_xnT_h + (size_t)b * HW * C;

    auto issue = [&](int ck) {
        const int k0 = ck * 64;
        const unsigned ws_o = (unsigned)((ck & 1) * TG_WS);
        const unsigned xs_o = (unsigned)(2 * TG_WS + (ck & 1) * TG_XS);
        #pragma unroll
        for (int r = 0; r < 8; ++r) {
            int f = r * 256 + tid;
            int c = f >> 3, ch = f & 7;
            cpa16(sbase + (ws_o + (unsigned)(c * 72 + ch * 8)) * 2,
                  g_W_h + (size_t)c * C + k0 + ch * 8);
        }
        #pragma unroll
        for (int r = 0; r < 4; ++r) {
            int f = r * 256 + tid;
            int p = f >> 3, ch = f & 7;
            cpa16(sbase + (xs_o + (unsigned)(p * 72 + ch * 8)) * 2,
                  xn_b + (size_t)(p0 + p) * C + k0 + ch * 8);
        }
        cpa_commit();
    };

    issue(0);

    float acc[4][8][4];
    #pragma unroll
    for (int m = 0; m < 4; ++m)
        #pragma unroll
        for (int t = 0; t < 8; ++t)
            #pragma unroll
            for (int r = 0; r < 4; ++r) acc[m][t][r] = 0.f;

    for (int ck = 0; ck < 4; ++ck) {
        if (ck + 1 < 4) {
            issue(ck + 1);
            asm volatile("cp.async.wait_group 1;" ::: "memory");
        } else {
            asm volatile("cp.async.wait_group 0;" ::: "memory");
        }
        __syncthreads();
        const unsigned ws_o = (unsigned)((ck & 1) * TG_WS);
        const unsigned xs_o = (unsigned)(2 * TG_WS + (ck & 1) * TG_XS);

        const unsigned aA = sbase + (ws_o + (unsigned)((wm * 64 + lrow) * 72) + lk8) * 2;
        const unsigned aB = sbase + (xs_o + (unsigned)((wn * 64 + lrow) * 72) + lk8) * 2;
        #pragma unroll
        for (int kk = 0; kk < 4; ++kk) {
            unsigned a[4][4], bb[4][4];
            #pragma unroll
            for (int m = 0; m < 4; ++m)
                ldsm_x4(a[m], aA + (unsigned)(m * 16 * 72 * 2) + kk * 32);
            #pragma unroll
            for (int n = 0; n < 4; ++n)
                ldsm_x4(bb[n], aB + (unsigned)(n * 16 * 72 * 2) + kk * 32);
            #pragma unroll
            for (int m = 0; m < 4; ++m)
                #pragma unroll
                for (int n = 0; n < 4; ++n) {
                    mma_f16(acc[m][n * 2 + 0], a[m], bb[n][0], bb[n][2]);
                    mma_f16(acc[m][n * 2 + 1], a[m], bb[n][1], bb[n][3]);
                }
        }
        __syncthreads();
    }

    __half* tb = g_t_h + (size_t)b * C * HW;
    const float* nb = g_norm + (size_t)b * HW;
    #pragma unroll
    for (int m = 0; m < 4; ++m) {
        const int c0 = wm * 64 + m * 16 + (lane >> 2);
        const float bo0 = __ldg(bias + c0);
        const float bo1 = __ldg(bias + c0 + 8);
        #pragma unroll
        for (int t = 0; t < 8; ++t) {
            const int p = p0 + wn * 64 + t * 8 + (lane & 3) * 2;
            float2 n2 = *reinterpret_cast<const float2*>(nb + p);
            *reinterpret_cast<unsigned*>(tb + (size_t)c0 * HW + p) =
                pack_h2(acc[m][t][0] * n2.x + bo0, acc[m][t][1] * n2.y + bo0);
            *reinterpret_cast<unsigned*>(tb + (size_t)(c0 + 8) * HW + p) =
                pack_h2(acc[m][t][2] * n2.x + bo1, acc[m][t][3] * n2.y + bo1);
        }
    }
}

// ---------------------------------------------------------------------------
// qbuild: per (pair, b): S = Xn_i Xn_j^T (128x128, K=256 in four 64-chunks,
//         double-buffered), Q = S^2 -> g_Q[i][j].  Pairs with ti >= tj.
// smem halves: xi 2x(128x72), xj 2x(128x72), qs 128x136 = 108,544 B -> 2 CTAs
// ---------------------------------------------------------------------------
#define QB_XI0 0
#define QB_XI1 9216
#define QB_XJ0 18432
#define QB_XJ1 27648
#define QB_QS  36864
#define Q_SMEM_H 54272

__global__ void __launch_bounds__(256, 2)
qbuild_kernel()
{
    extern __shared__ __half smh[];
    const unsigned sbase = smem_u32(smh);

    const int p   = blockIdx.x;
    const int b   = blockIdx.y;
    const int tid = threadIdx.x;
    const int wid = tid >> 5;
    const int lane = tid & 31;

    int ti = (int)((sqrtf(8.f * (float)p + 1.f) - 1.f) * 0.5f);
    while ((ti + 1) * (ti + 2) / 2 <= p) ++ti;
    while (ti * (ti + 1) / 2 > p) --ti;
    const int tj = p - ti * (ti + 1) / 2;
    const int i0 = ti * TI;
    const int j0 = tj * TI;

    const __half* xnT_b = g_xnT_h + (size_t)b * HW * C;

    const int wm = wid & 3;    // i-strip (32 rows)
    const int wn = wid >> 2;   // j-half (64 cols)
    const unsigned lrow = (unsigned)(lane & 15);
    const unsigned lk8  = (unsigned)((lane >> 4) * 8);

    auto issue = [&](int kc) {
        const int kb = kc * 64;
        const unsigned xi_o = (unsigned)((kc & 1) ? QB_XI1 : QB_XI0);
        const unsigned xj_o = (unsigned)((kc & 1) ? QB_XJ1 : QB_XJ0);
        #pragma unroll
        for (int r = 0; r < 4; ++r) {
            int f = r * 256 + tid;
            int row = f >> 3, ch = f & 7;
            cpa16(sbase + (xi_o + (unsigned)(row * 72 + ch * 8)) * 2,
                  xnT_b + (size_t)(i0 + row) * C + kb + ch * 8);
            cpa16(sbase + (xj_o + (unsigned)(row * 72 + ch * 8)) * 2,
                  xnT_b + (size_t)(j0 + row) * C + kb + ch * 8);
        }
        cpa_commit();
    };

    issue(0);

    float d[2][8][4];
    #pragma unroll
    for (int m = 0; m < 2; ++m)
        #pragma unroll
        for (int t = 0; t < 8; ++t)
            #pragma unroll
            for (int r = 0; r < 4; ++r) d[m][t][r] = 0.f;

    for (int kc = 0; kc < 4; ++kc) {
        if (kc + 1 < 4) {
            issue(kc + 1);
            asm volatile("cp.async.wait_group 1;" ::: "memory");
        } else {
            asm volatile("cp.async.wait_group 0;" ::: "memory");
        }
        __syncthreads();

        const unsigned xi_o = (unsigned)((kc & 1) ? QB_XI1 : QB_XI0);
        const unsigned xj_o = (unsigned)((kc & 1) ? QB_XJ1 : QB_XJ0);
        const unsigned aA = sbase + (xi_o + (unsigned)((wm * 32 + lrow) * 72) + lk8) * 2;
        const unsigned aB = sbase + (xj_o + (unsigned)((wn * 64 + lrow) * 72) + lk8) * 2;

        #pragma unroll
        for (int kk = 0; kk < 4; ++kk) {
            unsigned a[2][4];
            ldsm_x4(a[0], aA + kk * 32);
            ldsm_x4(a[1], aA + 16 * 72 * 2 + kk * 32);
            #pragma unroll
            for (int tt = 0; tt < 4; ++tt) {
                unsigned bb[4];
                ldsm_x4(bb, aB + (unsigned)(tt * 16 * 72 * 2) + kk * 32);
                #pragma unroll
                for (int m = 0; m < 2; ++m) {
                    mma_f16(d[m][tt * 2 + 0], a[m], bb[0], bb[2]);
                    mma_f16(d[m][tt * 2 + 1], a[m], bb[1], bb[3]);
                }
            }
        }
        __syncthreads();
    }

    {
        __half* qsm = smh + QB_QS;
        #pragma unroll
        for (int m = 0; m < 2; ++m) {
            const int r0 = wm * 32 + m * 16 + (lane >> 2);
            #pragma unroll
            for (int t = 0; t < 8; ++t) {
                const int col = wn * 64 + t * 8 + (lane & 3) * 2;
                *reinterpret_cast<unsigned*>(qsm + r0 * 136 + col) =
                    pack_h2(d[m][t][0] * d[m][t][0], d[m][t][1] * d[m][t][1]);
                *reinterpret_cast<unsigned*>(qsm + (r0 + 8) * 136 + col) =
                    pack_h2(d[m][t][2] * d[m][t][2], d[m][t][3] * d[m][t][3]);
            }
        }
    }
    __syncthreads();

    __half* Qb = g_Q + ((size_t)b * HW * HW);
    #pragma unroll
    for (int rr = 0; rr < 16; ++rr) {
        const int r = wid * 16 + rr;
        uint2 v = *reinterpret_cast<const uint2*>(smh + QB_QS + r * 136 + lane * 4);
        *reinterpret_cast<uint2*>(Qb + (size_t)(i0 + r) * HW + j0 + lane * 4) = v;
    }
}

// ---------------------------------------------------------------------------
// propagate: out[b][c][j] = sum_k t[c][k] * Q_sym[k][j]
// CTA: 128 c x 64 j, 128 threads (4 warps, each 32c x 64j), 4 CTAs/SM,
// K=4096 in 64-chunks, 2-stage cp.async pipeline.
// Q_sym: if kblk128 >= jblk128 read Q[k][j] (k-major, ldsm.trans);
//        else read Q[j][k] (j-major, ldsm). Both tiles 64x64 stride 72.
// smem halves: A 2x(128x72)=18432, B 2x(64x72)=9216 -> 55,296 B per CTA.
// ---------------------------------------------------------------------------
#define P_AS 9216
#define P_BS 4608
#define P_B_BASE (2 * P_AS)
#define P_SMEM_H (2 * P_AS + 2 * P_BS)

__global__ void __launch_bounds__(128, 4)
prop_kernel(float* __restrict__ out)
{
    extern __shared__ __half smh[];
    const unsigned sbase = smem_u32(smh);

    const int cs  = blockIdx.x & 1;          // c-strip (128)
    const int jt  = blockIdx.x >> 1;         // j-tile of 64
    const int b   = blockIdx.y;
    const int j0  = jt * 64;
    const int jb  = j0 >> 7;                 // 128-block index of j
    const int tid = threadIdx.x;
    const int wid = tid >> 5;                // warp c-quarter (32 rows)
    const int lane = tid & 31;

    const unsigned lrow = (unsigned)(lane & 15);
    const unsigned lk8  = (unsigned)((lane >> 4) * 8);
    const unsigned qrow = (unsigned)((((lane >> 3) & 1) * 8) + (lane & 7));

    const __half* t_b = g_t_h + (size_t)b * C * HW;
    const __half* Qb  = g_Q + ((size_t)b * HW * HW);

    auto issue = [&](int ck) {
        const int k0 = ck * 64;
        const int kb = k0 >> 7;
        const unsigned a_o = (unsigned)((ck & 1) * P_AS);
        const unsigned b_o = (unsigned)(P_B_BASE + (ck & 1) * P_BS);
        // A: t rows c (128) x 64 k
        #pragma unroll
        for (int r = 0; r < 8; ++r) {
            int f = r * 128 + tid;
            int row = f >> 3, ch = f & 7;
            cpa16(sbase + (a_o + (unsigned)(row * 72 + ch * 8)) * 2,
                  t_b + (size_t)(cs * 128 + row) * HW + k0 + ch * 8);
        }
        // B: 64x64 tile, stride 72; same copy shape for both orientations
        const __half* srcB = (kb >= jb) ? (Qb + (size_t)k0 * HW + j0)
                                        : (Qb + (size_t)j0 * HW + k0);
        #pragma unroll
        for (int r = 0; r < 4; ++r) {
            int f = r * 128 + tid;
            int row = f >> 3, ch = f & 7;
            cpa16(sbase + (b_o + (unsigned)(row * 72 + ch * 8)) * 2,
                  srcB + (size_t)row * HW + ch * 8);
        }
        cpa_commit();
    };

    issue(0);

    // Warp tile: 32 c-rows (2 m16 strips) x 64 j-cols (8 n8 tiles)
    float acc[2][8][4];
    #pragma unroll
    for (int s = 0; s < 2; ++s)
        #pragma unroll
        for (int t = 0; t < 8; ++t)
            #pragma unroll
            for (int r = 0; r < 4; ++r) acc[s][t][r] = 0.f;

    const unsigned aAinv = sbase + ((unsigned)((wid * 32 + lrow) * 72) + lk8) * 2;

    const int NCK = HW / 64;
    for (int ck = 0; ck < NCK; ++ck) {
        if (ck + 1 < NCK) {
            issue(ck + 1);
            asm volatile("cp.async.wait_group 1;" ::: "memory");
        } else {
            asm volatile("cp.async.wait_group 0;" ::: "memory");
        }
        __syncthreads();   // chunk ck resident for all warps

        const int k0 = ck * 64;
        const int kb = k0 >> 7;
        const unsigned a_o = (unsigned)((ck & 1) * P_AS);
        const unsigned b_o = (unsigned)(P_B_BASE + (ck & 1) * P_BS);
        const unsigned aA = aAinv + a_o * 2;

        if (kb >= jb) {
            // B is k-major Q[k][j]: trans fragments
            #pragma unroll
            for (int kk = 0; kk < 4; ++kk) {
                unsigned aa[2][4];
                ldsm_x4(aa[0], aA + kk * 32);
                ldsm_x4(aa[1], aA + 16 * 72 * 2 + kk * 32);
                #pragma unroll
                for (int tp = 0; tp < 4; ++tp) {
                    unsigned bq[4];
                    ldsm_x4t(bq, sbase + (b_o + (unsigned)((kk * 16 + qrow) * 72 +
                                                           tp * 16) + lk8) * 2);
                    #pragma unroll
                    for (int s = 0; s < 2; ++s) {
                        mma_f16(acc[s][tp * 2 + 0], aa[s], bq[0], bq[1]);
                        mma_f16(acc[s][tp * 2 + 1], aa[s], bq[2], bq[3]);
                    }
                }
            }
        } else {
            // B is j-major Q[j][k]: natural fragments
            #pragma unroll
            for (int kk = 0; kk < 4; ++kk) {
                unsigned aa[2][4];
                ldsm_x4(aa[0], aA + kk * 32);
                ldsm_x4(aa[1], aA + 16 * 72 * 2 + kk * 32);
                #pragma unroll
                for (int tt = 0; tt < 4; ++tt) {
                    unsigned bb[4];
                    ldsm_x4(bb, sbase + (b_o + (unsigned)((tt * 16 + lrow) * 72) +
                                         (unsigned)(kk * 16) + lk8) * 2);
                    #pragma unroll
                    for (int s = 0; s < 2; ++s) {
                        mma_f16(acc[s][tt * 2 + 0], aa[s], bb[0], bb[2]);
                        mma_f16(acc[s][tt * 2 + 1], aa[s], bb[1], bb[3]);
                    }
                }
            }
        }
        __syncthreads();   // buffer ck&1 free before refill in next iter
    }

    float* ob = out + (size_t)b * C * HW;
    #pragma unroll
    for (int s = 0; s < 2; ++s) {
        const int c0 = cs * 128 + wid * 32 + s * 16 + (lane >> 2);
        #pragma unroll
        for (int t = 0; t < 8; ++t) {
            const int col = j0 + t * 8 + (lane & 3) * 2;
            *reinterpret_cast<float2*>(ob + (size_t)c0 * HW + col) =
                make_float2(acc[s][t][0], acc[s][t][1]);
            *reinterpret_cast<float2*>(ob + (size_t)(c0 + 8) * HW + col) =
                make_float2(acc[s][t][2], acc[s][t][3]);
        }
    }
}

// ---------------------------------------------------------------------------
extern "C" void kernel_launch(void* const* d_in, const int* in_sizes, int n_in,
                              void* d_out, int out_size)
{
    const float* x    = (const float*)d_in[0];
    const float* W    = (const float*)d_in[1];
    const float* bias = (const float*)d_in[2];
    float* out        = (float*)d_out;

    const int PREP_SMEM = (C * 68 + 64) * 4;
    const int TG_SMEM   = TG_SMEM_H * 2;
    const int Q_SMEM    = Q_SMEM_H * 2;      // 108,544 B -> 2 CTAs/SM
    const int P_SMEM    = P_SMEM_H * 2;      // 55,296 B  -> 4 CTAs/SM (128 thr)

    cudaFuncSetAttribute(prep_kernel,   cudaFuncAttributeMaxDynamicSharedMemorySize, PREP_SMEM);
    cudaFuncSetAttribute(tgemm_kernel,  cudaFuncAttributeMaxDynamicSharedMemorySize, TG_SMEM);
    cudaFuncSetAttribute(qbuild_kernel, cudaFuncAttributeMaxDynamicSharedMemorySize, Q_SMEM);
    cudaFuncSetAttribute(prop_kernel,   cudaFuncAttributeMaxDynamicSharedMemorySize, P_SMEM);

    conv_w_kernel<<<64, 256>>>(W);

    dim3 g1(HW / PT, BATCH);
    prep_kernel<<<g1, 256, PREP_SMEM>>>(x);

    dim3 gt(HW / 128, BATCH);
    tgemm_kernel<<<gt, 256, TG_SMEM>>>(bias);

    dim3 gq(NPAIR, BATCH);
    qbuild_kernel<<<gq, 256, Q_SMEM>>>();

    dim3 gp(2 * (HW / 64), BATCH);
    prop_kernel<<<gp, 128, P_SMEM>>>(out);
}